// round 1
// baseline (speedup 1.0000x reference)
#include <cuda_runtime.h>

#define NODES 20000
#define BATCH 32
#define FEAT  64
#define OUTD  64
#define EIG   16
#define CHUNKS 80
#define CHUNK  250   // NODES / CHUNKS exactly

// Scratch (device globals — no allocation allowed)
__device__ float g_zpart[CHUNKS * BATCH * FEAT * EIG]; // 10.5 MB partials
__device__ float g_z[BATCH * FEAT * EIG];              // 128 KB
__device__ float g_w[BATCH * OUTD * EIG];              // 128 KB

// ---------------------------------------------------------------------------
// Phase 1: z[b,i,f] = sum_m V[m,f] * x[b,m,i]   (split-K over node chunks)
// grid (CHUNKS, BATCH), 128 threads. Thread: i-pair (i2) x f-quad (fq).
// ---------------------------------------------------------------------------
__global__ void k_project(const float* __restrict__ x, const float* __restrict__ V) {
    const int c = blockIdx.x, b = blockIdx.y;
    const int t  = threadIdx.x;
    const int i2 = t & 31;   // i = 2*i2, 2*i2+1
    const int fq = t >> 5;   // f = 4*fq .. 4*fq+3
    const float* xb = x + (size_t)(b * NODES) * FEAT + 2 * i2;
    const float* Vp = V + 4 * fq;

    float a00=0.f,a01=0.f,a02=0.f,a03=0.f;
    float a10=0.f,a11=0.f,a12=0.f,a13=0.f;

    const int m0 = c * CHUNK;
    #pragma unroll 2
    for (int m = m0; m < m0 + CHUNK; ++m) {
        float2 x2 = *(const float2*)(xb + (size_t)m * FEAT);
        float4 v4 = *(const float4*)(Vp + m * EIG);
        a00 += x2.x * v4.x; a01 += x2.x * v4.y; a02 += x2.x * v4.z; a03 += x2.x * v4.w;
        a10 += x2.y * v4.x; a11 += x2.y * v4.y; a12 += x2.y * v4.z; a13 += x2.y * v4.w;
    }
    float* dst = g_zpart + (size_t)(c * BATCH + b) * (FEAT * EIG);
    *(float4*)(dst + (2*i2+0) * EIG + 4*fq) = make_float4(a00,a01,a02,a03);
    *(float4*)(dst + (2*i2+1) * EIG + 4*fq) = make_float4(a10,a11,a12,a13);
}

// ---------------------------------------------------------------------------
// Reduce chunk partials: z = sum_c zpart[c]
// ---------------------------------------------------------------------------
__global__ void k_reduce() {
    const int idx = blockIdx.x * blockDim.x + threadIdx.x;  // 32768 threads total
    float s = 0.f;
    #pragma unroll 8
    for (int c = 0; c < CHUNKS; ++c)
        s += g_zpart[c * (BATCH * FEAT * EIG) + idx];
    g_z[idx] = s;
}

// ---------------------------------------------------------------------------
// Phase 2: w[b,j,e] = sum_{i,f} G[j,i,e,f] * z[b,i,f]
// grid OUTD (one block per j), 512 threads. Thread caches its G slice
// (2 i-rows x 16 f for one e) in registers; loops batches -> G read once.
// ---------------------------------------------------------------------------
__global__ void k_filter(const float* __restrict__ G) {
    const int j = blockIdx.x;
    const int t = threadIdx.x;      // 512
    const int e = t & 15;
    const int r = t >> 4;           // 0..31
    const int i0 = r * 2;

    // G[j, i, e, f] offset: ((j*FEAT + i)*EIG + e)*EIG + f
    const float* Gp = G + ((size_t)(j * FEAT + i0) * EIG + e) * EIG;
    float g0[16], g1[16];
    #pragma unroll
    for (int f4 = 0; f4 < 4; ++f4) {
        float4 a  = *(const float4*)(Gp + 4*f4);
        float4 bb = *(const float4*)(Gp + EIG*EIG + 4*f4);
        g0[4*f4+0]=a.x;  g0[4*f4+1]=a.y;  g0[4*f4+2]=a.z;  g0[4*f4+3]=a.w;
        g1[4*f4+0]=bb.x; g1[4*f4+1]=bb.y; g1[4*f4+2]=bb.z; g1[4*f4+3]=bb.w;
    }

    __shared__ float red[32][17];
    for (int b = 0; b < BATCH; ++b) {
        const float* zb = g_z + b * (FEAT * EIG) + i0 * EIG;
        float acc = 0.f;
        #pragma unroll
        for (int f4 = 0; f4 < 4; ++f4) {
            float4 z0 = *(const float4*)(zb + 4*f4);
            float4 z1 = *(const float4*)(zb + EIG + 4*f4);
            acc += g0[4*f4+0]*z0.x + g0[4*f4+1]*z0.y + g0[4*f4+2]*z0.z + g0[4*f4+3]*z0.w;
            acc += g1[4*f4+0]*z1.x + g1[4*f4+1]*z1.y + g1[4*f4+2]*z1.z + g1[4*f4+3]*z1.w;
        }
        red[r][e] = acc;
        __syncthreads();
        if (t < 16) {
            float s = 0.f;
            #pragma unroll
            for (int rr = 0; rr < 32; ++rr) s += red[rr][t];
            g_w[(b * OUTD + j) * EIG + t] = s;
        }
        __syncthreads();
    }
}

// ---------------------------------------------------------------------------
// Phase 3: out[b,n,j] = sum_e V[n,e] * w[b,j,e]
// grid (ceil(NODES/64), BATCH), 256 threads. 4n x 4j register tile per thread,
// V and w transposed into padded smem ([e][n] / [e][j]) for vector LDS.
// ---------------------------------------------------------------------------
#define NTILE 64
__global__ void k_output(const float* __restrict__ V, float* __restrict__ out) {
    const int tile = blockIdx.x, b = blockIdx.y;
    const int t = threadIdx.x;   // 256
    __shared__ __align__(16) float wt[EIG][68];
    __shared__ __align__(16) float vt[EIG][68];

    const int n0 = tile * NTILE;

    // w[b][j][e] -> wt[e][j]
    for (int k = t; k < OUTD * EIG; k += 256)
        wt[k & 15][k >> 4] = g_w[b * (OUTD * EIG) + k];
    // V[n][e] -> vt[e][n - n0], zero-padded past NODES
    for (int k = t; k < NTILE * EIG; k += 256) {
        int nl = k >> 4, e = k & 15;
        int n = n0 + nl;
        vt[e][nl] = (n < NODES) ? V[n * EIG + e] : 0.f;
    }
    __syncthreads();

    const int j0  = (t & 15) * 4;
    const int nl0 = (t >> 4) * 4;
    float acc[4][4];
    #pragma unroll
    for (int a = 0; a < 4; ++a)
        #pragma unroll
        for (int c = 0; c < 4; ++c) acc[a][c] = 0.f;

    #pragma unroll
    for (int e = 0; e < EIG; ++e) {
        float4 v4 = *(const float4*)&vt[e][nl0];
        float4 w4 = *(const float4*)&wt[e][j0];
        acc[0][0] += v4.x*w4.x; acc[0][1] += v4.x*w4.y; acc[0][2] += v4.x*w4.z; acc[0][3] += v4.x*w4.w;
        acc[1][0] += v4.y*w4.x; acc[1][1] += v4.y*w4.y; acc[1][2] += v4.y*w4.z; acc[1][3] += v4.y*w4.w;
        acc[2][0] += v4.z*w4.x; acc[2][1] += v4.z*w4.y; acc[2][2] += v4.z*w4.z; acc[2][3] += v4.z*w4.w;
        acc[3][0] += v4.w*w4.x; acc[3][1] += v4.w*w4.y; acc[3][2] += v4.w*w4.z; acc[3][3] += v4.w*w4.w;
    }

    float* ob = out + ((size_t)b * NODES + n0 + nl0) * OUTD + j0;
    #pragma unroll
    for (int ni = 0; ni < 4; ++ni) {
        if (n0 + nl0 + ni < NODES)
            *(float4*)(ob + (size_t)ni * OUTD) =
                make_float4(acc[ni][0], acc[ni][1], acc[ni][2], acc[ni][3]);
    }
}

extern "C" void kernel_launch(void* const* d_in, const int* in_sizes, int n_in,
                              void* d_out, int out_size) {
    const float* x = (const float*)d_in[0];   // (32, 20000, 64)
    const float* V = (const float*)d_in[1];   // (20000, 16)
    const float* G = (const float*)d_in[2];   // (64, 64, 16, 16)
    float* out = (float*)d_out;               // (32, 20000, 64)

    k_project<<<dim3(CHUNKS, BATCH), 128>>>(x, V);
    k_reduce<<<32, 1024>>>();
    k_filter<<<OUTD, 512>>>(G);
    k_output<<<dim3((NODES + NTILE - 1) / NTILE, BATCH), 256>>>(V, out);
}